// round 14
// baseline (speedup 1.0000x reference)
#include <cuda_runtime.h>
#include <math.h>
#include <stdint.h>

#define HH   256
#define NN   64
#define NP   32      // n-pairs
#define NG   16      // packed pair-groups (2 pairs per f32x2)
#define LL   2048
#define FF   1025
#define MM   1024
#define TPB  512

// ---- f32x2 packed helpers (Blackwell) ----
__device__ __forceinline__ uint64_t pk2(float lo, float hi) {
    uint64_t r; asm("mov.b64 %0,{%1,%2};" : "=l"(r) : "f"(lo), "f"(hi)); return r;
}
__device__ __forceinline__ void up2(uint64_t v, float& lo, float& hi) {
    asm("mov.b64 {%0,%1},%2;" : "=f"(lo), "=f"(hi) : "l"(v));
}
__device__ __forceinline__ uint64_t add2(uint64_t a, uint64_t b) {
    uint64_t d; asm("add.rn.f32x2 %0,%1,%2;" : "=l"(d) : "l"(a), "l"(b)); return d;
}
__device__ __forceinline__ uint64_t mul2(uint64_t a, uint64_t b) {
    uint64_t d; asm("mul.rn.f32x2 %0,%1,%2;" : "=l"(d) : "l"(a), "l"(b)); return d;
}
__device__ __forceinline__ uint64_t fma2(uint64_t a, uint64_t b, uint64_t c) {
    uint64_t d; asm("fma.rn.f32x2 %0,%1,%2,%3;" : "=l"(d) : "l"(a), "l"(b), "l"(c)); return d;
}
__device__ __forceinline__ uint64_t rcp2(uint64_t v) {
    float lo, hi; up2(v, lo, hi);
    float a, b;
    asm("rcp.approx.f32 %0,%1;" : "=f"(a) : "f"(lo));
    asm("rcp.approx.f32 %0,%1;" : "=f"(b) : "f"(hi));
    return pk2(a, b);
}
__device__ __forceinline__ float lanesum(uint64_t v) {
    float lo, hi; up2(v, lo, hi); return lo + hi;
}

// complex helpers on float2
__device__ __forceinline__ float2 cadd(float2 a, float2 b) { return make_float2(a.x + b.x, a.y + b.y); }
__device__ __forceinline__ float2 csub(float2 a, float2 b) { return make_float2(a.x - b.x, a.y - b.y); }
__device__ __forceinline__ float2 cmul(float2 a, float2 w) {
    return make_float2(a.x * w.x - a.y * w.y, a.x * w.y + a.y * w.x);
}

// Woodbury + bilinear gain epilogue for one frequency -> X in smem
__device__ __forceinline__ void woodbury(float A00r, float A00i, float A01r, float A01i,
                                         float A10r, float A10i, float A11r, float A11i,
                                         float dt, float gi, int f,
                                         float* __restrict__ Xr, float* __restrict__ Xi) {
    float r00r = dt * A00r, r00i = dt * A00i;
    float r01r = dt * A01r, r01i = dt * A01i;
    float r10r = dt * A10r, r10i = dt * A10i;
    float r11r = dt * A11r, r11i = dt * A11i;
    float numr = r01r * r10r - r01i * r10i;
    float numi = r01r * r10i + r01i * r10r;
    float denr = 1.0f + r11r;
    float deni = r11i;
    float dd   = denr * denr + deni * deni;
    float dinv; asm("rcp.approx.f32 %0,%1;" : "=f"(dinv) : "f"(dd));
    float qr = (numr * denr + numi * deni) * dinv;
    float qi = (numi * denr - numr * deni) * dinv;
    float xr = r00r - qr;
    float xi = r00i - qi;
    Xr[f] = xr - xi * gi;      // * (1 + i*gi), gi = tan(pi f / L)
    Xi[f] = xr * gi + xi;
}

// ---------------------------------------------------------------------------
// Fused kernel, one block per h, 512 threads, 2 blocks/SM (32 warps, 1 wave).
// Phase 1: Cauchy via common-denominator pole pairs, TWO passes of ONE freq.
//   Per-group constants packed AoS: pcg[g][20] u64 -> 10 uniform LDS.128
//   per group (was 19 LDS.64) to unbind the L1/LSU path.
// Phase 2: irfft(L=2048) via 1024-pt inverse FFT, radix-4 composed stages.
// ---------------------------------------------------------------------------
__global__ __launch_bounds__(TPB, 2)
void fused_kernel(const float* __restrict__ Cin, const float* __restrict__ Bin,
                  const float* __restrict__ Pin, const float* __restrict__ Win,
                  const float* __restrict__ logdt, float* __restrict__ out) {
    // raw per-n values (setup scratch)
    __shared__ __align__(16) float raw[9][NN];
    // AoS per-group constants: pcg[g][c] = u64 f32x2 over (pair 2g, pair 2g+1)
    // c: 0 S_i, 1 -S_r, 2 P_r, 3 P_i,
    //    4..7  A00 N0r,N0i,N1r,-N1i   8..11 A01   12..15 A10
    //    16,17 A11 N0r,N0i  18 A11 N1(real)  19 pad
    __shared__ __align__(16) uint64_t pcg[NG][20];
    __shared__ float2 tw[MM / 2];                // e^{+2*pi*i*t/1024}
    __shared__ float Xr[FF + 3], Xi[FF + 3];
    __shared__ float2 Zc[MM];

    const int h   = blockIdx.x;
    const int tid = threadIdx.x;
    const float dt = expf(logdt[h]);

    // twiddle table: one entry per thread
    {
        float s, c;
        sincospif((float)tid * (1.0f / 512.0f), &s, &c);
        tw[tid] = make_float2(c, s);
    }

    if (tid < NN) {
        const int base = h * (NN * 2) + tid * 2;
        float cr = Cin[base], ci = Cin[base + 1];
        float br = Bin[base], bi = Bin[base + 1];
        float pr = Pin[base], pi = Pin[base + 1];
        float wr = Win[base], wi = Win[base + 1];
        raw[0][tid] = wr * dt;             // w_dt
        raw[1][tid] = wi * dt;
        raw[2][tid] = br * cr - bi * ci;   // v00 = B*C
        raw[3][tid] = br * ci + bi * cr;
        raw[4][tid] = br * pr + bi * pi;   // v01 = B*conj(P)
        raw[5][tid] = bi * pr - br * pi;
        raw[6][tid] = pr * cr - pi * ci;   // v10 = P*C
        raw[7][tid] = pr * ci + pi * cr;
        raw[8][tid] = pr * pr + pi * pi;   // v11 = |P|^2 (real)
    }
    __syncthreads();

    if (tid < NP) {
        const int n0 = 2 * tid, n1 = 2 * tid + 1;
        // float slot for constant c of pair p: pcg flattened
        float* pf = (float*)&pcg[0][0];
        const int o = (tid >> 1) * 40 + (tid & 1);   // + 2*c
        float wr0 = raw[0][n0], wi0 = raw[1][n0];
        float wr1 = raw[0][n1], wi1 = raw[1][n1];
        pf[o + 0]  = wi0 + wi1;                      //  S_i
        pf[o + 2]  = -(wr0 + wr1);                   // -S_r
        pf[o + 4]  = wr0 * wr1 - wi0 * wi1;          //  P_r
        pf[o + 6]  = wr0 * wi1 + wi0 * wr1;          //  P_i
#pragma unroll
        for (int k = 0; k < 3; k++) {
            float ar0 = raw[2 + 2 * k][n0], ai0 = raw[3 + 2 * k][n0];
            float ar1 = raw[2 + 2 * k][n1], ai1 = raw[3 + 2 * k][n1];
            // N0 = -(a0*w1 + a1*w0), N1 = a0 + a1
            pf[o + 8 + 8 * k]  = -(ar0 * wr1 - ai0 * wi1 + ar1 * wr0 - ai1 * wi0);
            pf[o + 10 + 8 * k] = -(ar0 * wi1 + ai0 * wr1 + ar1 * wi0 + ai1 * wr0);
            pf[o + 12 + 8 * k] = ar0 + ar1;
            pf[o + 14 + 8 * k] = -(ai0 + ai1);
        }
        {   // A11: a real
            float a0 = raw[8][n0], a1 = raw[8][n1];
            pf[o + 32] = -(a0 * wr1 + a1 * wr0);     // N0r
            pf[o + 34] = -(a0 * wi1 + a1 * wi0);     // N0i
            pf[o + 36] = a0 + a1;                    // N1 (real)
            pf[o + 38] = 0.f;                        // pad
        }
    }
    __syncthreads();

    // Two passes of ONE frequency each: f = tid + 512*pass
#pragma unroll 1
    for (int pass = 0; pass < 2; pass++) {
        const int f = tid + 512 * pass;
        float y;
        {
            float s, c;
            sincospif((float)f * (1.0f / LL), &s, &c);
            y = 2.0f * __fdividef(s, c);
        }
        const uint64_t yk  = pk2(y, y);
        const uint64_t ny2 = pk2(-y * y, -y * y);

        uint64_t a00r = 0, a00i = 0, a01r = 0, a01i = 0;
        uint64_t a10r = 0, a10i = 0, a11r = 0, a11i = 0;

#pragma unroll 1
        for (int g = 0; g < NG; g++) {       // packed pair-group (2 pairs/lane)
            const ulonglong2* qg = (const ulonglong2*)&pcg[g][0];
            uint64_t sr, msi, si;
            {
                ulonglong2 cS = qg[0];                  // S_i, -S_r
                ulonglong2 cP = qg[1];                  // P_r, P_i
                uint64_t Dr  = fma2(yk, cS.x, add2(ny2, cP.x));
                uint64_t Di  = fma2(yk, cS.y, cP.y);
                uint64_t den = fma2(Dr, Dr, mul2(Di, Di));
                uint64_t inv = rcp2(den);
                sr  = mul2(Dr, inv);                    //  Re 1/D
                msi = mul2(Di, inv);                    // -Im 1/D
                si  = msi ^ 0x8000000080000000ULL;      //  Im 1/D (ALU)
            }
            // kind 00
            {
                ulonglong2 c0 = qg[2];                  // N0r, N0i
                ulonglong2 c1 = qg[3];                  // N1r, -N1i
                uint64_t Nr = fma2(yk, c1.y, c0.x);
                uint64_t Ni = fma2(yk, c1.x, c0.y);
                a00r = fma2(Nr, sr, a00r); a00r = fma2(Ni, msi, a00r);
                a00i = fma2(Nr, si, a00i); a00i = fma2(Ni, sr,  a00i);
            }
            // kind 01
            {
                ulonglong2 c0 = qg[4];
                ulonglong2 c1 = qg[5];
                uint64_t Nr = fma2(yk, c1.y, c0.x);
                uint64_t Ni = fma2(yk, c1.x, c0.y);
                a01r = fma2(Nr, sr, a01r); a01r = fma2(Ni, msi, a01r);
                a01i = fma2(Nr, si, a01i); a01i = fma2(Ni, sr,  a01i);
            }
            // kind 10
            {
                ulonglong2 c0 = qg[6];
                ulonglong2 c1 = qg[7];
                uint64_t Nr = fma2(yk, c1.y, c0.x);
                uint64_t Ni = fma2(yk, c1.x, c0.y);
                a10r = fma2(Nr, sr, a10r); a10r = fma2(Ni, msi, a10r);
                a10i = fma2(Nr, si, a10i); a10i = fma2(Ni, sr,  a10i);
            }
            // kind 11 (N1 real)
            {
                ulonglong2 c0 = qg[8];                  // N0r, N0i
                ulonglong2 c1 = qg[9];                  // N1, pad
                uint64_t Nr = c0.x;
                uint64_t Ni = fma2(yk, c1.x, c0.y);
                a11r = fma2(Nr, sr, a11r); a11r = fma2(Ni, msi, a11r);
                a11i = fma2(Nr, si, a11i); a11i = fma2(Ni, sr,  a11i);
            }
        }

        woodbury(lanesum(a00r), lanesum(a00i),
                 lanesum(a01r), lanesum(a01i),
                 lanesum(a10r), lanesum(a10i),
                 lanesum(a11r), lanesum(a11i),
                 dt, 0.5f * y, f, Xr, Xi);
    }

    // Nyquist bin f = L/2 (removable singularity): limit = 0.5*dt*sum_n v00r
    if (tid == 0) {
        const float* pf = (const float*)&pcg[0][0];
        float sr = 0.f;
        for (int p = 0; p < NP; p++)
            sr += pf[(p >> 1) * 40 + 12 + (p & 1)];   // A00 N1r = v00r pair sums
        Xr[MM] = 0.5f * dt * sr;
        Xi[MM] = 0.f;
    }
    __syncthreads();

    // ---- Phase 2: irfft via 1024-pt complex inverse FFT ----
    const float scl = 1.0f / 2048.0f;
#pragma unroll
    for (int j = 0; j < 2; j++) {
        int k = tid + 512 * j;
        float Xkx = Xr[k],      Xky = Xi[k];
        float Xmx = Xr[MM - k], Xmy = Xi[MM - k];
        if (k == 0) { Xky = 0.f; Xmy = 0.f; }   // drop imag of DC & Nyquist
        float er  = (Xkx + Xmx) * scl;
        float ei  = (Xky - Xmy) * scl;
        float pr  = (Xkx - Xmx) * scl;
        float pi_ = (Xky + Xmy) * scl;
        float s, c;
        sincospif((float)k * (1.0f / MM), &s, &c);  // e^{+i*pi*k/1024}
        float Or = pr * c - pi_ * s;
        float Oi = pr * s + pi_ * c;
        Zc[k] = make_float2(er - Oi, ei + Or);      // Z = E + i*O
    }
    __syncthreads();

    // 10 radix-2 DIF stages as 5 fused double-stages; 256 active threads.
#pragma unroll
    for (int q = 256; q >= 1; q >>= 2) {
        if (tid < 256) {
            const int m = tid & (q - 1);
            const int g = ((tid - m) << 2) + m;
            const int t1 = m * (256 / q);

            float2 a = Zc[g], b = Zc[g + q], c = Zc[g + 2 * q], d = Zc[g + 3 * q];

            float2 w1 = tw[t1];
            float2 w2 = tw[t1 + 256];
            float2 t0v = cadd(a, c);
            float2 t1v = cmul(csub(a, c), w1);
            float2 t2v = cadd(b, d);
            float2 t3v = cmul(csub(b, d), w2);

            float2 w3 = tw[m * (512 / q)];
            Zc[g]         = cadd(t0v, t2v);
            Zc[g + q]     = cmul(csub(t0v, t2v), w3);
            Zc[g + 2 * q] = cadd(t1v, t3v);
            Zc[g + 3 * q] = cmul(csub(t1v, t3v), w3);
        }
        __syncthreads();
    }

    float2* out2 = reinterpret_cast<float2*>(out + h * LL);
#pragma unroll
    for (int j = 0; j < 2; j++) {
        int p = tid + 512 * j;
        int n = __brev((unsigned)p) >> 22;   // 10-bit reverse
        out2[n] = Zc[p];
    }
}

extern "C" void kernel_launch(void* const* d_in, const int* in_sizes, int n_in,
                              void* d_out, int out_size) {
    (void)in_sizes; (void)n_in; (void)out_size;
    const float* C  = (const float*)d_in[0];
    const float* B  = (const float*)d_in[1];
    const float* P  = (const float*)d_in[2];
    const float* W  = (const float*)d_in[3];
    const float* ld = (const float*)d_in[4];
    fused_kernel<<<HH, TPB>>>(C, B, P, W, ld, (float*)d_out);
}

// round 15
// speedup vs baseline: 1.6231x; 1.6231x over previous
#include <cuda_runtime.h>
#include <math.h>
#include <stdint.h>

#define HH   256
#define NN   64
#define NP   32      // n-pairs
#define NG   16      // packed pair-groups (2 pairs per f32x2)
#define LL   2048
#define FF   1025
#define MM   1024
#define TPB  256

// ---- f32x2 packed helpers (Blackwell) ----
__device__ __forceinline__ uint64_t pk2(float lo, float hi) {
    uint64_t r; asm("mov.b64 %0,{%1,%2};" : "=l"(r) : "f"(lo), "f"(hi)); return r;
}
__device__ __forceinline__ void up2(uint64_t v, float& lo, float& hi) {
    asm("mov.b64 {%0,%1},%2;" : "=f"(lo), "=f"(hi) : "l"(v));
}
__device__ __forceinline__ uint64_t add2(uint64_t a, uint64_t b) {
    uint64_t d; asm("add.rn.f32x2 %0,%1,%2;" : "=l"(d) : "l"(a), "l"(b)); return d;
}
__device__ __forceinline__ uint64_t mul2(uint64_t a, uint64_t b) {
    uint64_t d; asm("mul.rn.f32x2 %0,%1,%2;" : "=l"(d) : "l"(a), "l"(b)); return d;
}
__device__ __forceinline__ uint64_t fma2(uint64_t a, uint64_t b, uint64_t c) {
    uint64_t d; asm("fma.rn.f32x2 %0,%1,%2,%3;" : "=l"(d) : "l"(a), "l"(b), "l"(c)); return d;
}
__device__ __forceinline__ uint64_t rcp2(uint64_t v) {
    float lo, hi; up2(v, lo, hi);
    float a, b;
    asm("rcp.approx.f32 %0,%1;" : "=f"(a) : "f"(lo));
    asm("rcp.approx.f32 %0,%1;" : "=f"(b) : "f"(hi));
    return pk2(a, b);
}
__device__ __forceinline__ float lanesum(uint64_t v) {
    float lo, hi; up2(v, lo, hi); return lo + hi;
}

// complex helpers on float2
__device__ __forceinline__ float2 cadd(float2 a, float2 b) { return make_float2(a.x + b.x, a.y + b.y); }
__device__ __forceinline__ float2 csub(float2 a, float2 b) { return make_float2(a.x - b.x, a.y - b.y); }
__device__ __forceinline__ float2 cmul(float2 a, float2 w) {
    return make_float2(a.x * w.x - a.y * w.y, a.x * w.y + a.y * w.x);
}

// Woodbury + bilinear gain epilogue for one frequency -> X in smem
__device__ __forceinline__ void woodbury(float A00r, float A00i, float A01r, float A01i,
                                         float A10r, float A10i, float A11r, float A11i,
                                         float dt, float gi, int f,
                                         float* __restrict__ Xr, float* __restrict__ Xi) {
    float r00r = dt * A00r, r00i = dt * A00i;
    float r01r = dt * A01r, r01i = dt * A01i;
    float r10r = dt * A10r, r10i = dt * A10i;
    float r11r = dt * A11r, r11i = dt * A11i;
    float numr = r01r * r10r - r01i * r10i;
    float numi = r01r * r10i + r01i * r10r;
    float denr = 1.0f + r11r;
    float deni = r11i;
    float dd   = denr * denr + deni * deni;
    float dinv; asm("rcp.approx.f32 %0,%1;" : "=f"(dinv) : "f"(dd));
    float qr = (numr * denr + numi * deni) * dinv;
    float qi = (numi * denr - numr * deni) * dinv;
    float xr = r00r - qr;
    float xi = r00i - qi;
    Xr[f] = xr - xi * gi;      // * (1 + i*gi), gi = tan(pi f / L)
    Xi[f] = xr * gi + xi;
}

// ---------------------------------------------------------------------------
// Fused kernel, one block per h, 256 threads, 2 blocks/SM (single wave).
// Phase 1: Cauchy via common-denominator pole pairs, two passes of 2 freqs.
//   g-loop unrolled x2: two groups' broadcast LDS + math interleaved to
//   cover the LDS->FMA and rcp latency chains (R12 ran it serial).
// Phase 2: irfft(L=2048) via 1024-pt inverse FFT, radix-4 composed stages.
// ---------------------------------------------------------------------------
__global__ __launch_bounds__(TPB, 2)
void fused_kernel(const float* __restrict__ Cin, const float* __restrict__ Bin,
                  const float* __restrict__ Pin, const float* __restrict__ Win,
                  const float* __restrict__ logdt, float* __restrict__ out) {
    // raw per-n values (setup scratch)
    __shared__ __align__(16) float raw[9][NN];
    // per-pair constants (SoA):
    // 0 S_i, 1 -S_r, 2 P_r, 3 P_i,
    // 4..7   A00: N0r, N0i, N1r, -N1i
    // 8..11  A01: N0r, N0i, N1r, -N1i
    // 12..15 A10: N0r, N0i, N1r, -N1i
    // 16..18 A11: N0r, N0i, N1 (real)
    __shared__ __align__(16) float pc[19][NP];
    __shared__ float2 tw[MM / 2];                // e^{+2*pi*i*t/1024}
    __shared__ float Xr[FF + 3], Xi[FF + 3];
    __shared__ float2 Zc[MM];

    const int h   = blockIdx.x;
    const int tid = threadIdx.x;
    const float dt = expf(logdt[h]);

    // twiddle table: 2 entries per thread
#pragma unroll
    for (int j = 0; j < 2; j++) {
        int t = tid + 256 * j;
        float s, c;
        sincospif((float)t * (1.0f / 512.0f), &s, &c);
        tw[t] = make_float2(c, s);
    }

    if (tid < NN) {
        const int base = h * (NN * 2) + tid * 2;
        float cr = Cin[base], ci = Cin[base + 1];
        float br = Bin[base], bi = Bin[base + 1];
        float pr = Pin[base], pi = Pin[base + 1];
        float wr = Win[base], wi = Win[base + 1];
        raw[0][tid] = wr * dt;             // w_dt
        raw[1][tid] = wi * dt;
        raw[2][tid] = br * cr - bi * ci;   // v00 = B*C
        raw[3][tid] = br * ci + bi * cr;
        raw[4][tid] = br * pr + bi * pi;   // v01 = B*conj(P)
        raw[5][tid] = bi * pr - br * pi;
        raw[6][tid] = pr * cr - pi * ci;   // v10 = P*C
        raw[7][tid] = pr * ci + pi * cr;
        raw[8][tid] = pr * pr + pi * pi;   // v11 = |P|^2 (real)
    }
    __syncthreads();

    if (tid < NP) {
        const int n0 = 2 * tid, n1 = 2 * tid + 1;
        float wr0 = raw[0][n0], wi0 = raw[1][n0];
        float wr1 = raw[0][n1], wi1 = raw[1][n1];
        pc[0][tid] = wi0 + wi1;                      //  S_i
        pc[1][tid] = -(wr0 + wr1);                   // -S_r
        pc[2][tid] = wr0 * wr1 - wi0 * wi1;          //  P_r
        pc[3][tid] = wr0 * wi1 + wi0 * wr1;          //  P_i
#pragma unroll
        for (int k = 0; k < 3; k++) {
            float ar0 = raw[2 + 2 * k][n0], ai0 = raw[3 + 2 * k][n0];
            float ar1 = raw[2 + 2 * k][n1], ai1 = raw[3 + 2 * k][n1];
            // N0 = -(a0*w1 + a1*w0), N1 = a0 + a1
            pc[4 + 4 * k][tid] = -(ar0 * wr1 - ai0 * wi1 + ar1 * wr0 - ai1 * wi0);
            pc[5 + 4 * k][tid] = -(ar0 * wi1 + ai0 * wr1 + ar1 * wi0 + ai1 * wr0);
            pc[6 + 4 * k][tid] = ar0 + ar1;
            pc[7 + 4 * k][tid] = -(ai0 + ai1);
        }
        {   // A11: a real
            float a0 = raw[8][n0], a1 = raw[8][n1];
            pc[16][tid] = -(a0 * wr1 + a1 * wr0);    // N0r
            pc[17][tid] = -(a0 * wi1 + a1 * wi0);    // N0i
            pc[18][tid] = a0 + a1;                   // N1 (real)
        }
    }
    __syncthreads();

    const uint64_t* q0  = (const uint64_t*)&pc[0][0];
    const uint64_t* q1  = (const uint64_t*)&pc[1][0];
    const uint64_t* q2  = (const uint64_t*)&pc[2][0];
    const uint64_t* q3  = (const uint64_t*)&pc[3][0];
    const uint64_t* q4  = (const uint64_t*)&pc[4][0];
    const uint64_t* q5  = (const uint64_t*)&pc[5][0];
    const uint64_t* q6  = (const uint64_t*)&pc[6][0];
    const uint64_t* q7  = (const uint64_t*)&pc[7][0];
    const uint64_t* q8  = (const uint64_t*)&pc[8][0];
    const uint64_t* q9  = (const uint64_t*)&pc[9][0];
    const uint64_t* q10 = (const uint64_t*)&pc[10][0];
    const uint64_t* q11 = (const uint64_t*)&pc[11][0];
    const uint64_t* q12 = (const uint64_t*)&pc[12][0];
    const uint64_t* q13 = (const uint64_t*)&pc[13][0];
    const uint64_t* q14 = (const uint64_t*)&pc[14][0];
    const uint64_t* q15 = (const uint64_t*)&pc[15][0];
    const uint64_t* q16 = (const uint64_t*)&pc[16][0];
    const uint64_t* q17 = (const uint64_t*)&pc[17][0];
    const uint64_t* q18 = (const uint64_t*)&pc[18][0];

    // Two passes of 2 frequencies each: f = tid + 512*pass + 256*j
#pragma unroll 1
    for (int pass = 0; pass < 2; pass++) {
        float zis[2];
        uint64_t yk[2], ny2[2];
#pragma unroll
        for (int j = 0; j < 2; j++) {
            int f = tid + 512 * pass + 256 * j;
            float s, c;
            sincospif((float)f * (1.0f / LL), &s, &c);
            float y = 2.0f * __fdividef(s, c);
            zis[j] = y;
            yk[j]  = pk2(y, y);
            ny2[j] = pk2(-y * y, -y * y);
        }

        uint64_t a00r[2] = {0, 0}, a00i[2] = {0, 0};
        uint64_t a01r[2] = {0, 0}, a01i[2] = {0, 0};
        uint64_t a10r[2] = {0, 0}, a10i[2] = {0, 0};
        uint64_t a11r[2] = {0, 0}, a11i[2] = {0, 0};

#pragma unroll 2
        for (int g = 0; g < NG; g++) {       // packed pair-group (2 pairs/lane)
            // reciprocal of the quadratic denominator for both freqs
            uint64_t sr[2], msi[2], si[2];
            {
                uint64_t Si = q0[g], nSr = q1[g], Pr = q2[g], Pi = q3[g];
#pragma unroll
                for (int j = 0; j < 2; j++) {
                    uint64_t t   = add2(ny2[j], Pr);
                    uint64_t Dr  = fma2(yk[j], Si,  t);
                    uint64_t Di  = fma2(yk[j], nSr, Pi);
                    uint64_t den = fma2(Dr, Dr, mul2(Di, Di));
                    uint64_t inv = rcp2(den);
                    sr[j]  = mul2(Dr, inv);                    //  Re 1/D
                    msi[j] = mul2(Di, inv);                    // -Im 1/D
                    si[j]  = msi[j] ^ 0x8000000080000000ULL;   //  Im 1/D (ALU)
                }
            }
            // kind 00
            {
                uint64_t N0r = q4[g], N0i = q5[g], N1r = q6[g], nN1i = q7[g];
#pragma unroll
                for (int j = 0; j < 2; j++) {
                    uint64_t Nr = fma2(yk[j], nN1i, N0r);
                    uint64_t Ni = fma2(yk[j], N1r,  N0i);
                    a00r[j] = fma2(Nr, sr[j], a00r[j]); a00r[j] = fma2(Ni, msi[j], a00r[j]);
                    a00i[j] = fma2(Nr, si[j], a00i[j]); a00i[j] = fma2(Ni, sr[j],  a00i[j]);
                }
            }
            // kind 01
            {
                uint64_t N0r = q8[g], N0i = q9[g], N1r = q10[g], nN1i = q11[g];
#pragma unroll
                for (int j = 0; j < 2; j++) {
                    uint64_t Nr = fma2(yk[j], nN1i, N0r);
                    uint64_t Ni = fma2(yk[j], N1r,  N0i);
                    a01r[j] = fma2(Nr, sr[j], a01r[j]); a01r[j] = fma2(Ni, msi[j], a01r[j]);
                    a01i[j] = fma2(Nr, si[j], a01i[j]); a01i[j] = fma2(Ni, sr[j],  a01i[j]);
                }
            }
            // kind 10
            {
                uint64_t N0r = q12[g], N0i = q13[g], N1r = q14[g], nN1i = q15[g];
#pragma unroll
                for (int j = 0; j < 2; j++) {
                    uint64_t Nr = fma2(yk[j], nN1i, N0r);
                    uint64_t Ni = fma2(yk[j], N1r,  N0i);
                    a10r[j] = fma2(Nr, sr[j], a10r[j]); a10r[j] = fma2(Ni, msi[j], a10r[j]);
                    a10i[j] = fma2(Nr, si[j], a10i[j]); a10i[j] = fma2(Ni, sr[j],  a10i[j]);
                }
            }
            // kind 11 (N1 real)
            {
                uint64_t N0r = q16[g], N0i = q17[g], N1 = q18[g];
#pragma unroll
                for (int j = 0; j < 2; j++) {
                    uint64_t Ni = fma2(yk[j], N1, N0i);
                    a11r[j] = fma2(N0r, sr[j], a11r[j]); a11r[j] = fma2(Ni, msi[j], a11r[j]);
                    a11i[j] = fma2(N0r, si[j], a11i[j]); a11i[j] = fma2(Ni, sr[j],  a11i[j]);
                }
            }
        }

#pragma unroll
        for (int j = 0; j < 2; j++) {
            int f = tid + 512 * pass + 256 * j;
            woodbury(lanesum(a00r[j]), lanesum(a00i[j]),
                     lanesum(a01r[j]), lanesum(a01i[j]),
                     lanesum(a10r[j]), lanesum(a10i[j]),
                     lanesum(a11r[j]), lanesum(a11i[j]),
                     dt, 0.5f * zis[j], f, Xr, Xi);
        }
    }

    // Nyquist bin f = L/2 (removable singularity): limit = 0.5*dt*sum_n v00r
    if (tid == 0) {
        float sr = 0.f;
        for (int p = 0; p < NP; p++) sr += pc[6][p];   // pair N1r(00) = v00r sums
        Xr[MM] = 0.5f * dt * sr;
        Xi[MM] = 0.f;
    }
    __syncthreads();

    // ---- Phase 2: irfft via 1024-pt complex inverse FFT ----
    const float scl = 1.0f / 2048.0f;
#pragma unroll
    for (int j = 0; j < 4; j++) {
        int k = tid + 256 * j;
        float Xkx = Xr[k],      Xky = Xi[k];
        float Xmx = Xr[MM - k], Xmy = Xi[MM - k];
        if (k == 0) { Xky = 0.f; Xmy = 0.f; }   // drop imag of DC & Nyquist
        float er  = (Xkx + Xmx) * scl;
        float ei  = (Xky - Xmy) * scl;
        float pr  = (Xkx - Xmx) * scl;
        float pi_ = (Xky + Xmy) * scl;
        float s, c;
        sincospif((float)k * (1.0f / MM), &s, &c);  // e^{+i*pi*k/1024}
        float Or = pr * c - pi_ * s;
        float Oi = pr * s + pi_ * c;
        Zc[k] = make_float2(er - Oi, ei + Or);      // Z = E + i*O
    }
    __syncthreads();

    // 10 radix-2 DIF stages executed as 5 fused double-stages.
#pragma unroll
    for (int q = 256; q >= 1; q >>= 2) {
        const int m = tid & (q - 1);
        const int g = ((tid - m) << 2) + m;
        const int t1 = m * (256 / q);

        float2 a = Zc[g], b = Zc[g + q], c = Zc[g + 2 * q], d = Zc[g + 3 * q];

        float2 w1 = tw[t1];
        float2 w2 = tw[t1 + 256];
        float2 t0v = cadd(a, c);
        float2 t1v = cmul(csub(a, c), w1);
        float2 t2v = cadd(b, d);
        float2 t3v = cmul(csub(b, d), w2);

        float2 w3 = tw[m * (512 / q)];
        Zc[g]         = cadd(t0v, t2v);
        Zc[g + q]     = cmul(csub(t0v, t2v), w3);
        Zc[g + 2 * q] = cadd(t1v, t3v);
        Zc[g + 3 * q] = cmul(csub(t1v, t3v), w3);
        __syncthreads();
    }

    float2* out2 = reinterpret_cast<float2*>(out + h * LL);
#pragma unroll
    for (int j = 0; j < 4; j++) {
        int p = tid + 256 * j;
        int n = __brev((unsigned)p) >> 22;   // 10-bit reverse
        out2[n] = Zc[p];
    }
}

extern "C" void kernel_launch(void* const* d_in, const int* in_sizes, int n_in,
                              void* d_out, int out_size) {
    (void)in_sizes; (void)n_in; (void)out_size;
    const float* C  = (const float*)d_in[0];
    const float* B  = (const float*)d_in[1];
    const float* P  = (const float*)d_in[2];
    const float* W  = (const float*)d_in[3];
    const float* ld = (const float*)d_in[4];
    fused_kernel<<<HH, TPB>>>(C, B, P, W, ld, (float*)d_out);
}

// round 16
// speedup vs baseline: 1.7575x; 1.0828x over previous
#include <cuda_runtime.h>
#include <math.h>
#include <stdint.h>

#define HH   256
#define NN   64
#define NP   32      // n-pairs
#define NG   16      // packed pair-groups (2 pairs per f32x2)
#define LL   2048
#define FF   1025
#define MM   1024
#define TPB  256

// padded Zc index: kills >2-way bank conflicts in late FFT stages
#define ZPAD(i) ((i) + ((i) >> 4))

// ---- f32x2 packed helpers (Blackwell) ----
__device__ __forceinline__ uint64_t pk2(float lo, float hi) {
    uint64_t r; asm("mov.b64 %0,{%1,%2};" : "=l"(r) : "f"(lo), "f"(hi)); return r;
}
__device__ __forceinline__ void up2(uint64_t v, float& lo, float& hi) {
    asm("mov.b64 {%0,%1},%2;" : "=f"(lo), "=f"(hi) : "l"(v));
}
__device__ __forceinline__ uint64_t add2(uint64_t a, uint64_t b) {
    uint64_t d; asm("add.rn.f32x2 %0,%1,%2;" : "=l"(d) : "l"(a), "l"(b)); return d;
}
__device__ __forceinline__ uint64_t mul2(uint64_t a, uint64_t b) {
    uint64_t d; asm("mul.rn.f32x2 %0,%1,%2;" : "=l"(d) : "l"(a), "l"(b)); return d;
}
__device__ __forceinline__ uint64_t fma2(uint64_t a, uint64_t b, uint64_t c) {
    uint64_t d; asm("fma.rn.f32x2 %0,%1,%2,%3;" : "=l"(d) : "l"(a), "l"(b), "l"(c)); return d;
}
__device__ __forceinline__ uint64_t rcp2(uint64_t v) {
    float lo, hi; up2(v, lo, hi);
    float a, b;
    asm("rcp.approx.f32 %0,%1;" : "=f"(a) : "f"(lo));
    asm("rcp.approx.f32 %0,%1;" : "=f"(b) : "f"(hi));
    return pk2(a, b);
}
__device__ __forceinline__ float lanesum(uint64_t v) {
    float lo, hi; up2(v, lo, hi); return lo + hi;
}

// complex helpers on float2
__device__ __forceinline__ float2 cadd(float2 a, float2 b) { return make_float2(a.x + b.x, a.y + b.y); }
__device__ __forceinline__ float2 csub(float2 a, float2 b) { return make_float2(a.x - b.x, a.y - b.y); }
__device__ __forceinline__ float2 cmul(float2 a, float2 w) {
    return make_float2(a.x * w.x - a.y * w.y, a.x * w.y + a.y * w.x);
}

// Woodbury + bilinear gain epilogue for one frequency -> X in smem
__device__ __forceinline__ void woodbury(float A00r, float A00i, float A01r, float A01i,
                                         float A10r, float A10i, float A11r, float A11i,
                                         float dt, float gi, int f,
                                         float* __restrict__ Xr, float* __restrict__ Xi) {
    float r00r = dt * A00r, r00i = dt * A00i;
    float r01r = dt * A01r, r01i = dt * A01i;
    float r10r = dt * A10r, r10i = dt * A10i;
    float r11r = dt * A11r, r11i = dt * A11i;
    float numr = r01r * r10r - r01i * r10i;
    float numi = r01r * r10i + r01i * r10r;
    float denr = 1.0f + r11r;
    float deni = r11i;
    float dd   = denr * denr + deni * deni;
    float dinv; asm("rcp.approx.f32 %0,%1;" : "=f"(dinv) : "f"(dd));
    float qr = (numr * denr + numi * deni) * dinv;
    float qi = (numi * denr - numr * deni) * dinv;
    float xr = r00r - qr;
    float xi = r00i - qi;
    Xr[f] = xr - xi * gi;      // * (1 + i*gi), gi = tan(pi f / L)
    Xi[f] = xr * gi + xi;
}

// ---------------------------------------------------------------------------
// Fused kernel, one block per h, 256 threads, 2 blocks/SM (single wave).
// Phase 1: Cauchy via common-denominator pole pairs (R15 mainloop, untouched —
//   it runs at the FMA throughput floor).
// Phase 2: irfft(L=2048) via 1024-pt inverse FFT, radix-4 composed stages.
//   NEW: per-stage conflict-free twiddle tables (w1 only; w2 = i*w1 free,
//   w3 = w1^2 in regs) + padded Zc indexing. Removes the 8/16/32-way smem
//   bank conflicts that dominated the FFT phase.
// ---------------------------------------------------------------------------
__global__ __launch_bounds__(TPB, 2)
void fused_kernel(const float* __restrict__ Cin, const float* __restrict__ Bin,
                  const float* __restrict__ Pin, const float* __restrict__ Win,
                  const float* __restrict__ logdt, float* __restrict__ out) {
    // raw per-n values (setup scratch)
    __shared__ __align__(16) float raw[9][NN];
    // per-pair constants (SoA):
    // 0 S_i, 1 -S_r, 2 P_r, 3 P_i,
    // 4..7   A00: N0r, N0i, N1r, -N1i
    // 8..11  A01: N0r, N0i, N1r, -N1i
    // 12..15 A10: N0r, N0i, N1r, -N1i
    // 16..18 A11: N0r, N0i, N1 (real)
    __shared__ __align__(16) float pc[19][NP];
    // per-stage w1 twiddles, laid out by m (conflict-free):
    // stage q=256 at off 0 (256), q=64 at 256 (64), q=16 at 320 (16),
    // q=4 at 336 (4), q=1 at 340 (1) -> 341 entries. w1 = e^{+i*pi*m/(2q)}
    __shared__ float2 stw[344];
    __shared__ float Xr[FF + 3], Xi[FF + 3];
    __shared__ float2 Zc[ZPAD(MM - 1) + 1 + 8];

    const int h   = blockIdx.x;
    const int tid = threadIdx.x;
    const float dt = expf(logdt[h]);

    // build per-stage twiddle tables (<=2 entries per thread)
    for (int t = tid; t < 341; t += TPB) {
        int m; float rq2;
        if (t < 256)      { m = t;       rq2 = 1.0f / 512.0f; }
        else if (t < 320) { m = t - 256; rq2 = 1.0f / 128.0f; }
        else if (t < 336) { m = t - 320; rq2 = 1.0f / 32.0f;  }
        else if (t < 340) { m = t - 336; rq2 = 1.0f / 8.0f;   }
        else              { m = 0;       rq2 = 1.0f / 2.0f;   }
        float s, c;
        sincospif((float)m * rq2, &s, &c);   // e^{+i*pi*m/(2q)}
        stw[t] = make_float2(c, s);
    }

    if (tid < NN) {
        const int base = h * (NN * 2) + tid * 2;
        float cr = Cin[base], ci = Cin[base + 1];
        float br = Bin[base], bi = Bin[base + 1];
        float pr = Pin[base], pi = Pin[base + 1];
        float wr = Win[base], wi = Win[base + 1];
        raw[0][tid] = wr * dt;             // w_dt
        raw[1][tid] = wi * dt;
        raw[2][tid] = br * cr - bi * ci;   // v00 = B*C
        raw[3][tid] = br * ci + bi * cr;
        raw[4][tid] = br * pr + bi * pi;   // v01 = B*conj(P)
        raw[5][tid] = bi * pr - br * pi;
        raw[6][tid] = pr * cr - pi * ci;   // v10 = P*C
        raw[7][tid] = pr * ci + pi * cr;
        raw[8][tid] = pr * pr + pi * pi;   // v11 = |P|^2 (real)
    }
    __syncthreads();

    if (tid < NP) {
        const int n0 = 2 * tid, n1 = 2 * tid + 1;
        float wr0 = raw[0][n0], wi0 = raw[1][n0];
        float wr1 = raw[0][n1], wi1 = raw[1][n1];
        pc[0][tid] = wi0 + wi1;                      //  S_i
        pc[1][tid] = -(wr0 + wr1);                   // -S_r
        pc[2][tid] = wr0 * wr1 - wi0 * wi1;          //  P_r
        pc[3][tid] = wr0 * wi1 + wi0 * wr1;          //  P_i
#pragma unroll
        for (int k = 0; k < 3; k++) {
            float ar0 = raw[2 + 2 * k][n0], ai0 = raw[3 + 2 * k][n0];
            float ar1 = raw[2 + 2 * k][n1], ai1 = raw[3 + 2 * k][n1];
            // N0 = -(a0*w1 + a1*w0), N1 = a0 + a1
            pc[4 + 4 * k][tid] = -(ar0 * wr1 - ai0 * wi1 + ar1 * wr0 - ai1 * wi0);
            pc[5 + 4 * k][tid] = -(ar0 * wi1 + ai0 * wr1 + ar1 * wi0 + ai1 * wr0);
            pc[6 + 4 * k][tid] = ar0 + ar1;
            pc[7 + 4 * k][tid] = -(ai0 + ai1);
        }
        {   // A11: a real
            float a0 = raw[8][n0], a1 = raw[8][n1];
            pc[16][tid] = -(a0 * wr1 + a1 * wr0);    // N0r
            pc[17][tid] = -(a0 * wi1 + a1 * wi0);    // N0i
            pc[18][tid] = a0 + a1;                   // N1 (real)
        }
    }
    __syncthreads();

    const uint64_t* q0  = (const uint64_t*)&pc[0][0];
    const uint64_t* q1  = (const uint64_t*)&pc[1][0];
    const uint64_t* q2  = (const uint64_t*)&pc[2][0];
    const uint64_t* q3  = (const uint64_t*)&pc[3][0];
    const uint64_t* q4  = (const uint64_t*)&pc[4][0];
    const uint64_t* q5  = (const uint64_t*)&pc[5][0];
    const uint64_t* q6  = (const uint64_t*)&pc[6][0];
    const uint64_t* q7  = (const uint64_t*)&pc[7][0];
    const uint64_t* q8  = (const uint64_t*)&pc[8][0];
    const uint64_t* q9  = (const uint64_t*)&pc[9][0];
    const uint64_t* q10 = (const uint64_t*)&pc[10][0];
    const uint64_t* q11 = (const uint64_t*)&pc[11][0];
    const uint64_t* q12 = (const uint64_t*)&pc[12][0];
    const uint64_t* q13 = (const uint64_t*)&pc[13][0];
    const uint64_t* q14 = (const uint64_t*)&pc[14][0];
    const uint64_t* q15 = (const uint64_t*)&pc[15][0];
    const uint64_t* q16 = (const uint64_t*)&pc[16][0];
    const uint64_t* q17 = (const uint64_t*)&pc[17][0];
    const uint64_t* q18 = (const uint64_t*)&pc[18][0];

    // Two passes of 2 frequencies each: f = tid + 512*pass + 256*j
#pragma unroll 1
    for (int pass = 0; pass < 2; pass++) {
        float zis[2];
        uint64_t yk[2], ny2[2];
#pragma unroll
        for (int j = 0; j < 2; j++) {
            int f = tid + 512 * pass + 256 * j;
            float s, c;
            sincospif((float)f * (1.0f / LL), &s, &c);
            float y = 2.0f * __fdividef(s, c);
            zis[j] = y;
            yk[j]  = pk2(y, y);
            ny2[j] = pk2(-y * y, -y * y);
        }

        uint64_t a00r[2] = {0, 0}, a00i[2] = {0, 0};
        uint64_t a01r[2] = {0, 0}, a01i[2] = {0, 0};
        uint64_t a10r[2] = {0, 0}, a10i[2] = {0, 0};
        uint64_t a11r[2] = {0, 0}, a11i[2] = {0, 0};

#pragma unroll 2
        for (int g = 0; g < NG; g++) {       // packed pair-group (2 pairs/lane)
            // reciprocal of the quadratic denominator for both freqs
            uint64_t sr[2], msi[2], si[2];
            {
                uint64_t Si = q0[g], nSr = q1[g], Pr = q2[g], Pi = q3[g];
#pragma unroll
                for (int j = 0; j < 2; j++) {
                    uint64_t t   = add2(ny2[j], Pr);
                    uint64_t Dr  = fma2(yk[j], Si,  t);
                    uint64_t Di  = fma2(yk[j], nSr, Pi);
                    uint64_t den = fma2(Dr, Dr, mul2(Di, Di));
                    uint64_t inv = rcp2(den);
                    sr[j]  = mul2(Dr, inv);                    //  Re 1/D
                    msi[j] = mul2(Di, inv);                    // -Im 1/D
                    si[j]  = msi[j] ^ 0x8000000080000000ULL;   //  Im 1/D (ALU)
                }
            }
            // kind 00
            {
                uint64_t N0r = q4[g], N0i = q5[g], N1r = q6[g], nN1i = q7[g];
#pragma unroll
                for (int j = 0; j < 2; j++) {
                    uint64_t Nr = fma2(yk[j], nN1i, N0r);
                    uint64_t Ni = fma2(yk[j], N1r,  N0i);
                    a00r[j] = fma2(Nr, sr[j], a00r[j]); a00r[j] = fma2(Ni, msi[j], a00r[j]);
                    a00i[j] = fma2(Nr, si[j], a00i[j]); a00i[j] = fma2(Ni, sr[j],  a00i[j]);
                }
            }
            // kind 01
            {
                uint64_t N0r = q8[g], N0i = q9[g], N1r = q10[g], nN1i = q11[g];
#pragma unroll
                for (int j = 0; j < 2; j++) {
                    uint64_t Nr = fma2(yk[j], nN1i, N0r);
                    uint64_t Ni = fma2(yk[j], N1r,  N0i);
                    a01r[j] = fma2(Nr, sr[j], a01r[j]); a01r[j] = fma2(Ni, msi[j], a01r[j]);
                    a01i[j] = fma2(Nr, si[j], a01i[j]); a01i[j] = fma2(Ni, sr[j],  a01i[j]);
                }
            }
            // kind 10
            {
                uint64_t N0r = q12[g], N0i = q13[g], N1r = q14[g], nN1i = q15[g];
#pragma unroll
                for (int j = 0; j < 2; j++) {
                    uint64_t Nr = fma2(yk[j], nN1i, N0r);
                    uint64_t Ni = fma2(yk[j], N1r,  N0i);
                    a10r[j] = fma2(Nr, sr[j], a10r[j]); a10r[j] = fma2(Ni, msi[j], a10r[j]);
                    a10i[j] = fma2(Nr, si[j], a10i[j]); a10i[j] = fma2(Ni, sr[j],  a10i[j]);
                }
            }
            // kind 11 (N1 real)
            {
                uint64_t N0r = q16[g], N0i = q17[g], N1 = q18[g];
#pragma unroll
                for (int j = 0; j < 2; j++) {
                    uint64_t Ni = fma2(yk[j], N1, N0i);
                    a11r[j] = fma2(N0r, sr[j], a11r[j]); a11r[j] = fma2(Ni, msi[j], a11r[j]);
                    a11i[j] = fma2(N0r, si[j], a11i[j]); a11i[j] = fma2(Ni, sr[j],  a11i[j]);
                }
            }
        }

#pragma unroll
        for (int j = 0; j < 2; j++) {
            int f = tid + 512 * pass + 256 * j;
            woodbury(lanesum(a00r[j]), lanesum(a00i[j]),
                     lanesum(a01r[j]), lanesum(a01i[j]),
                     lanesum(a10r[j]), lanesum(a10i[j]),
                     lanesum(a11r[j]), lanesum(a11i[j]),
                     dt, 0.5f * zis[j], f, Xr, Xi);
        }
    }

    // Nyquist bin f = L/2 (removable singularity): limit = 0.5*dt*sum_n v00r
    if (tid == 0) {
        float sr = 0.f;
        for (int p = 0; p < NP; p++) sr += pc[6][p];   // pair N1r(00) = v00r sums
        Xr[MM] = 0.5f * dt * sr;
        Xi[MM] = 0.f;
    }
    __syncthreads();

    // ---- Phase 2: irfft via 1024-pt complex inverse FFT ----
    const float scl = 1.0f / 2048.0f;
#pragma unroll
    for (int j = 0; j < 4; j++) {
        int k = tid + 256 * j;
        float Xkx = Xr[k],      Xky = Xi[k];
        float Xmx = Xr[MM - k], Xmy = Xi[MM - k];
        if (k == 0) { Xky = 0.f; Xmy = 0.f; }   // drop imag of DC & Nyquist
        float er  = (Xkx + Xmx) * scl;
        float ei  = (Xky - Xmy) * scl;
        float pr  = (Xkx - Xmx) * scl;
        float pi_ = (Xky + Xmy) * scl;
        float s, c;
        sincospif((float)k * (1.0f / MM), &s, &c);  // e^{+i*pi*k/1024}
        float Or = pr * c - pi_ * s;
        float Oi = pr * s + pi_ * c;
        Zc[ZPAD(k)] = make_float2(er - Oi, ei + Or); // Z = E + i*O
    }
    __syncthreads();

    // 10 radix-2 DIF stages as 5 fused double-stages.
    // w1 from per-stage table; w2 = i*w1 (inlined); w3 = w1^2 (regs).
    {
        int off = 0;
#pragma unroll
        for (int q = 256; q >= 1; q >>= 2) {
            const int m = tid & (q - 1);
            const int g = ((tid - m) << 2) + m;

            float2 a = Zc[ZPAD(g)],         b = Zc[ZPAD(g + q)];
            float2 c = Zc[ZPAD(g + 2 * q)], d = Zc[ZPAD(g + 3 * q)];

            float2 w1 = stw[off + m];
            float2 t0v = cadd(a, c);
            float2 t1v = cmul(csub(a, c), w1);
            float2 bd  = csub(b, d);
            // t3v = (b-d) * (i*w1)
            float2 t3v = make_float2(-w1.y * bd.x - w1.x * bd.y,
                                      w1.x * bd.x - w1.y * bd.y);
            float2 t2v = cadd(b, d);

            float2 w3 = make_float2(w1.x * w1.x - w1.y * w1.y,
                                    2.0f * w1.x * w1.y);   // w1^2
            Zc[ZPAD(g)]         = cadd(t0v, t2v);
            Zc[ZPAD(g + q)]     = cmul(csub(t0v, t2v), w3);
            Zc[ZPAD(g + 2 * q)] = cadd(t1v, t3v);
            Zc[ZPAD(g + 3 * q)] = cmul(csub(t1v, t3v), w3);
            __syncthreads();
            off += q;
        }
    }

    float2* out2 = reinterpret_cast<float2*>(out + h * LL);
#pragma unroll
    for (int j = 0; j < 4; j++) {
        int p = tid + 256 * j;
        int n = __brev((unsigned)p) >> 22;   // 10-bit reverse
        out2[n] = Zc[ZPAD(p)];
    }
}

extern "C" void kernel_launch(void* const* d_in, const int* in_sizes, int n_in,
                              void* d_out, int out_size) {
    (void)in_sizes; (void)n_in; (void)out_size;
    const float* C  = (const float*)d_in[0];
    const float* B  = (const float*)d_in[1];
    const float* P  = (const float*)d_in[2];
    const float* W  = (const float*)d_in[3];
    const float* ld = (const float*)d_in[4];
    fused_kernel<<<HH, TPB>>>(C, B, P, W, ld, (float*)d_out);
}

// round 17
// speedup vs baseline: 1.7602x; 1.0015x over previous
#include <cuda_runtime.h>
#include <math.h>
#include <stdint.h>

#define HH   256
#define NN   64
#define NP   32      // n-pairs
#define NG   16      // packed pair-groups (2 pairs per f32x2)
#define LL   2048
#define FF   1025
#define MM   1024
#define TPB  256

// padded Zc index: kills >2-way bank conflicts in mid FFT stages
#define ZPAD(i) ((i) + ((i) >> 4))

// ---- f32x2 packed helpers (Blackwell) ----
__device__ __forceinline__ uint64_t pk2(float lo, float hi) {
    uint64_t r; asm("mov.b64 %0,{%1,%2};" : "=l"(r) : "f"(lo), "f"(hi)); return r;
}
__device__ __forceinline__ void up2(uint64_t v, float& lo, float& hi) {
    asm("mov.b64 {%0,%1},%2;" : "=f"(lo), "=f"(hi) : "l"(v));
}
__device__ __forceinline__ uint64_t add2(uint64_t a, uint64_t b) {
    uint64_t d; asm("add.rn.f32x2 %0,%1,%2;" : "=l"(d) : "l"(a), "l"(b)); return d;
}
__device__ __forceinline__ uint64_t mul2(uint64_t a, uint64_t b) {
    uint64_t d; asm("mul.rn.f32x2 %0,%1,%2;" : "=l"(d) : "l"(a), "l"(b)); return d;
}
__device__ __forceinline__ uint64_t fma2(uint64_t a, uint64_t b, uint64_t c) {
    uint64_t d; asm("fma.rn.f32x2 %0,%1,%2,%3;" : "=l"(d) : "l"(a), "l"(b), "l"(c)); return d;
}
__device__ __forceinline__ uint64_t rcp2(uint64_t v) {
    float lo, hi; up2(v, lo, hi);
    float a, b;
    asm("rcp.approx.f32 %0,%1;" : "=f"(a) : "f"(lo));
    asm("rcp.approx.f32 %0,%1;" : "=f"(b) : "f"(hi));
    return pk2(a, b);
}
__device__ __forceinline__ float lanesum(uint64_t v) {
    float lo, hi; up2(v, lo, hi); return lo + hi;
}

// complex helpers on float2
__device__ __forceinline__ float2 cadd(float2 a, float2 b) { return make_float2(a.x + b.x, a.y + b.y); }
__device__ __forceinline__ float2 csub(float2 a, float2 b) { return make_float2(a.x - b.x, a.y - b.y); }
__device__ __forceinline__ float2 cmul(float2 a, float2 w) {
    return make_float2(a.x * w.x - a.y * w.y, a.x * w.y + a.y * w.x);
}

// Woodbury + bilinear gain epilogue for one frequency -> X in smem
__device__ __forceinline__ void woodbury(float A00r, float A00i, float A01r, float A01i,
                                         float A10r, float A10i, float A11r, float A11i,
                                         float dt, float gi, int f,
                                         float* __restrict__ Xr, float* __restrict__ Xi) {
    float r00r = dt * A00r, r00i = dt * A00i;
    float r01r = dt * A01r, r01i = dt * A01i;
    float r10r = dt * A10r, r10i = dt * A10i;
    float r11r = dt * A11r, r11i = dt * A11i;
    float numr = r01r * r10r - r01i * r10i;
    float numi = r01r * r10i + r01i * r10r;
    float denr = 1.0f + r11r;
    float deni = r11i;
    float dd   = denr * denr + deni * deni;
    float dinv; asm("rcp.approx.f32 %0,%1;" : "=f"(dinv) : "f"(dd));
    float qr = (numr * denr + numi * deni) * dinv;
    float qi = (numi * denr - numr * deni) * dinv;
    float xr = r00r - qr;
    float xi = r00i - qi;
    Xr[f] = xr - xi * gi;      // * (1 + i*gi), gi = tan(pi f / L)
    Xi[f] = xr * gi + xi;
}

// ---------------------------------------------------------------------------
// Fused kernel, one block per h, 256 threads, 2 blocks/SM (single wave).
// Phase 1: Cauchy via common-denominator pole pairs (mainloop at FMA floor).
// Phase 2: irfft(L=2048) via 1024-pt inverse FFT, radix-4 composed stages.
//   NEW: first double-stage (q=256) fused with the Z-build in registers;
//   last double-stage (q=1, twiddle-free) fused with the bit-reversed gmem
//   store. 4 barriers instead of 6, two fewer smem round-trips.
// ---------------------------------------------------------------------------
__global__ __launch_bounds__(TPB, 2)
void fused_kernel(const float* __restrict__ Cin, const float* __restrict__ Bin,
                  const float* __restrict__ Pin, const float* __restrict__ Win,
                  const float* __restrict__ logdt, float* __restrict__ out) {
    // raw per-n values (setup scratch)
    __shared__ __align__(16) float raw[9][NN];
    // per-pair constants (SoA):
    // 0 S_i, 1 -S_r, 2 P_r, 3 P_i,
    // 4..7   A00: N0r, N0i, N1r, -N1i
    // 8..11  A01: N0r, N0i, N1r, -N1i
    // 12..15 A10: N0r, N0i, N1r, -N1i
    // 16..18 A11: N0r, N0i, N1 (real)
    __shared__ __align__(16) float pc[19][NP];
    // per-stage w1 twiddles by m (conflict-free):
    // q=256 at 0 (256 entries), q=64 at 256 (64), q=16 at 320 (16), q=4 at 336 (4)
    __shared__ float2 stw[344];
    __shared__ float Xr[FF + 3], Xi[FF + 3];
    __shared__ float2 Zc[ZPAD(MM - 1) + 1 + 8];

    const int h   = blockIdx.x;
    const int tid = threadIdx.x;
    const float dt = expf(logdt[h]);

    // build per-stage twiddle tables
    for (int t = tid; t < 340; t += TPB) {
        int m; float rq2;
        if (t < 256)      { m = t;       rq2 = 1.0f / 512.0f; }
        else if (t < 320) { m = t - 256; rq2 = 1.0f / 128.0f; }
        else if (t < 336) { m = t - 320; rq2 = 1.0f / 32.0f;  }
        else              { m = t - 336; rq2 = 1.0f / 8.0f;   }
        float s, c;
        sincospif((float)m * rq2, &s, &c);   // e^{+i*pi*m/(2q)}
        stw[t] = make_float2(c, s);
    }

    if (tid < NN) {
        const int base = h * (NN * 2) + tid * 2;
        float cr = Cin[base], ci = Cin[base + 1];
        float br = Bin[base], bi = Bin[base + 1];
        float pr = Pin[base], pi = Pin[base + 1];
        float wr = Win[base], wi = Win[base + 1];
        raw[0][tid] = wr * dt;             // w_dt
        raw[1][tid] = wi * dt;
        raw[2][tid] = br * cr - bi * ci;   // v00 = B*C
        raw[3][tid] = br * ci + bi * cr;
        raw[4][tid] = br * pr + bi * pi;   // v01 = B*conj(P)
        raw[5][tid] = bi * pr - br * pi;
        raw[6][tid] = pr * cr - pi * ci;   // v10 = P*C
        raw[7][tid] = pr * ci + pi * cr;
        raw[8][tid] = pr * pr + pi * pi;   // v11 = |P|^2 (real)
    }
    __syncthreads();

    if (tid < NP) {
        const int n0 = 2 * tid, n1 = 2 * tid + 1;
        float wr0 = raw[0][n0], wi0 = raw[1][n0];
        float wr1 = raw[0][n1], wi1 = raw[1][n1];
        pc[0][tid] = wi0 + wi1;                      //  S_i
        pc[1][tid] = -(wr0 + wr1);                   // -S_r
        pc[2][tid] = wr0 * wr1 - wi0 * wi1;          //  P_r
        pc[3][tid] = wr0 * wi1 + wi0 * wr1;          //  P_i
#pragma unroll
        for (int k = 0; k < 3; k++) {
            float ar0 = raw[2 + 2 * k][n0], ai0 = raw[3 + 2 * k][n0];
            float ar1 = raw[2 + 2 * k][n1], ai1 = raw[3 + 2 * k][n1];
            // N0 = -(a0*w1 + a1*w0), N1 = a0 + a1
            pc[4 + 4 * k][tid] = -(ar0 * wr1 - ai0 * wi1 + ar1 * wr0 - ai1 * wi0);
            pc[5 + 4 * k][tid] = -(ar0 * wi1 + ai0 * wr1 + ar1 * wi0 + ai1 * wr0);
            pc[6 + 4 * k][tid] = ar0 + ar1;
            pc[7 + 4 * k][tid] = -(ai0 + ai1);
        }
        {   // A11: a real
            float a0 = raw[8][n0], a1 = raw[8][n1];
            pc[16][tid] = -(a0 * wr1 + a1 * wr0);    // N0r
            pc[17][tid] = -(a0 * wi1 + a1 * wi0);    // N0i
            pc[18][tid] = a0 + a1;                   // N1 (real)
        }
    }
    __syncthreads();

    const uint64_t* q0  = (const uint64_t*)&pc[0][0];
    const uint64_t* q1  = (const uint64_t*)&pc[1][0];
    const uint64_t* q2  = (const uint64_t*)&pc[2][0];
    const uint64_t* q3  = (const uint64_t*)&pc[3][0];
    const uint64_t* q4  = (const uint64_t*)&pc[4][0];
    const uint64_t* q5  = (const uint64_t*)&pc[5][0];
    const uint64_t* q6  = (const uint64_t*)&pc[6][0];
    const uint64_t* q7  = (const uint64_t*)&pc[7][0];
    const uint64_t* q8  = (const uint64_t*)&pc[8][0];
    const uint64_t* q9  = (const uint64_t*)&pc[9][0];
    const uint64_t* q10 = (const uint64_t*)&pc[10][0];
    const uint64_t* q11 = (const uint64_t*)&pc[11][0];
    const uint64_t* q12 = (const uint64_t*)&pc[12][0];
    const uint64_t* q13 = (const uint64_t*)&pc[13][0];
    const uint64_t* q14 = (const uint64_t*)&pc[14][0];
    const uint64_t* q15 = (const uint64_t*)&pc[15][0];
    const uint64_t* q16 = (const uint64_t*)&pc[16][0];
    const uint64_t* q17 = (const uint64_t*)&pc[17][0];
    const uint64_t* q18 = (const uint64_t*)&pc[18][0];

    // Two passes of 2 frequencies each: f = tid + 512*pass + 256*j
#pragma unroll 1
    for (int pass = 0; pass < 2; pass++) {
        float zis[2];
        uint64_t yk[2], ny2[2];
#pragma unroll
        for (int j = 0; j < 2; j++) {
            int f = tid + 512 * pass + 256 * j;
            float s, c;
            sincospif((float)f * (1.0f / LL), &s, &c);
            float y = 2.0f * __fdividef(s, c);
            zis[j] = y;
            yk[j]  = pk2(y, y);
            ny2[j] = pk2(-y * y, -y * y);
        }

        uint64_t a00r[2] = {0, 0}, a00i[2] = {0, 0};
        uint64_t a01r[2] = {0, 0}, a01i[2] = {0, 0};
        uint64_t a10r[2] = {0, 0}, a10i[2] = {0, 0};
        uint64_t a11r[2] = {0, 0}, a11i[2] = {0, 0};

#pragma unroll 2
        for (int g = 0; g < NG; g++) {       // packed pair-group (2 pairs/lane)
            uint64_t sr[2], msi[2], si[2];
            {
                uint64_t Si = q0[g], nSr = q1[g], Pr = q2[g], Pi = q3[g];
#pragma unroll
                for (int j = 0; j < 2; j++) {
                    uint64_t t   = add2(ny2[j], Pr);
                    uint64_t Dr  = fma2(yk[j], Si,  t);
                    uint64_t Di  = fma2(yk[j], nSr, Pi);
                    uint64_t den = fma2(Dr, Dr, mul2(Di, Di));
                    uint64_t inv = rcp2(den);
                    sr[j]  = mul2(Dr, inv);                    //  Re 1/D
                    msi[j] = mul2(Di, inv);                    // -Im 1/D
                    si[j]  = msi[j] ^ 0x8000000080000000ULL;   //  Im 1/D (ALU)
                }
            }
            // kind 00
            {
                uint64_t N0r = q4[g], N0i = q5[g], N1r = q6[g], nN1i = q7[g];
#pragma unroll
                for (int j = 0; j < 2; j++) {
                    uint64_t Nr = fma2(yk[j], nN1i, N0r);
                    uint64_t Ni = fma2(yk[j], N1r,  N0i);
                    a00r[j] = fma2(Nr, sr[j], a00r[j]); a00r[j] = fma2(Ni, msi[j], a00r[j]);
                    a00i[j] = fma2(Nr, si[j], a00i[j]); a00i[j] = fma2(Ni, sr[j],  a00i[j]);
                }
            }
            // kind 01
            {
                uint64_t N0r = q8[g], N0i = q9[g], N1r = q10[g], nN1i = q11[g];
#pragma unroll
                for (int j = 0; j < 2; j++) {
                    uint64_t Nr = fma2(yk[j], nN1i, N0r);
                    uint64_t Ni = fma2(yk[j], N1r,  N0i);
                    a01r[j] = fma2(Nr, sr[j], a01r[j]); a01r[j] = fma2(Ni, msi[j], a01r[j]);
                    a01i[j] = fma2(Nr, si[j], a01i[j]); a01i[j] = fma2(Ni, sr[j],  a01i[j]);
                }
            }
            // kind 10
            {
                uint64_t N0r = q12[g], N0i = q13[g], N1r = q14[g], nN1i = q15[g];
#pragma unroll
                for (int j = 0; j < 2; j++) {
                    uint64_t Nr = fma2(yk[j], nN1i, N0r);
                    uint64_t Ni = fma2(yk[j], N1r,  N0i);
                    a10r[j] = fma2(Nr, sr[j], a10r[j]); a10r[j] = fma2(Ni, msi[j], a10r[j]);
                    a10i[j] = fma2(Nr, si[j], a10i[j]); a10i[j] = fma2(Ni, sr[j],  a10i[j]);
                }
            }
            // kind 11 (N1 real)
            {
                uint64_t N0r = q16[g], N0i = q17[g], N1 = q18[g];
#pragma unroll
                for (int j = 0; j < 2; j++) {
                    uint64_t Ni = fma2(yk[j], N1, N0i);
                    a11r[j] = fma2(N0r, sr[j], a11r[j]); a11r[j] = fma2(Ni, msi[j], a11r[j]);
                    a11i[j] = fma2(N0r, si[j], a11i[j]); a11i[j] = fma2(Ni, sr[j],  a11i[j]);
                }
            }
        }

#pragma unroll
        for (int j = 0; j < 2; j++) {
            int f = tid + 512 * pass + 256 * j;
            woodbury(lanesum(a00r[j]), lanesum(a00i[j]),
                     lanesum(a01r[j]), lanesum(a01i[j]),
                     lanesum(a10r[j]), lanesum(a10i[j]),
                     lanesum(a11r[j]), lanesum(a11i[j]),
                     dt, 0.5f * zis[j], f, Xr, Xi);
        }
    }

    // Nyquist bin f = L/2 (removable singularity): limit = 0.5*dt*sum_n v00r
    if (tid == 0) {
        float sr = 0.f;
        for (int p = 0; p < NP; p++) sr += pc[6][p];   // pair N1r(00) = v00r sums
        Xr[MM] = 0.5f * dt * sr;
        Xi[MM] = 0.f;
    }
    __syncthreads();

    // ---- Phase 2: irfft via 1024-pt complex inverse FFT ----
    // Z-build + first double-stage (q=256, m=tid) fused in registers.
    {
        const float scl = 1.0f / 2048.0f;
        float2 z[4];
#pragma unroll
        for (int j = 0; j < 4; j++) {
            int k = tid + 256 * j;
            float Xkx = Xr[k],      Xky = Xi[k];
            float Xmx = Xr[MM - k], Xmy = Xi[MM - k];
            if (k == 0) { Xky = 0.f; Xmy = 0.f; }   // drop imag of DC & Nyquist
            float er  = (Xkx + Xmx) * scl;
            float ei  = (Xky - Xmy) * scl;
            float pr  = (Xkx - Xmx) * scl;
            float pi_ = (Xky + Xmy) * scl;
            float s, c;
            sincospif((float)k * (1.0f / MM), &s, &c);  // e^{+i*pi*k/1024}
            float Or = pr * c - pi_ * s;
            float Oi = pr * s + pi_ * c;
            z[j] = make_float2(er - Oi, ei + Or);       // Z = E + i*O
        }
        // q=256 double-stage in registers
        float2 w1 = stw[tid];
        float2 t0v = cadd(z[0], z[2]);
        float2 t1v = cmul(csub(z[0], z[2]), w1);
        float2 bd  = csub(z[1], z[3]);
        float2 t3v = make_float2(-w1.y * bd.x - w1.x * bd.y,
                                  w1.x * bd.x - w1.y * bd.y);   // (b-d)*(i*w1)
        float2 t2v = cadd(z[1], z[3]);
        float2 w3 = make_float2(w1.x * w1.x - w1.y * w1.y,
                                2.0f * w1.x * w1.y);            // w1^2
        Zc[ZPAD(tid)]       = cadd(t0v, t2v);
        Zc[ZPAD(tid + 256)] = cmul(csub(t0v, t2v), w3);
        Zc[ZPAD(tid + 512)] = cadd(t1v, t3v);
        Zc[ZPAD(tid + 768)] = cmul(csub(t1v, t3v), w3);
    }
    __syncthreads();

    // middle double-stages q = 64, 16, 4 via smem
    {
        int off = 256;
#pragma unroll
        for (int q = 64; q >= 4; q >>= 2) {
            const int m = tid & (q - 1);
            const int g = ((tid - m) << 2) + m;

            float2 a = Zc[ZPAD(g)],         b = Zc[ZPAD(g + q)];
            float2 c = Zc[ZPAD(g + 2 * q)], d = Zc[ZPAD(g + 3 * q)];

            float2 w1 = stw[off + m];
            float2 t0v = cadd(a, c);
            float2 t1v = cmul(csub(a, c), w1);
            float2 bd  = csub(b, d);
            float2 t3v = make_float2(-w1.y * bd.x - w1.x * bd.y,
                                      w1.x * bd.x - w1.y * bd.y);
            float2 t2v = cadd(b, d);
            float2 w3 = make_float2(w1.x * w1.x - w1.y * w1.y,
                                    2.0f * w1.x * w1.y);
            Zc[ZPAD(g)]         = cadd(t0v, t2v);
            Zc[ZPAD(g + q)]     = cmul(csub(t0v, t2v), w3);
            Zc[ZPAD(g + 2 * q)] = cadd(t1v, t3v);
            Zc[ZPAD(g + 3 * q)] = cmul(csub(t1v, t3v), w3);
            __syncthreads();
            off += q;
        }
    }

    // last double-stage q=1 (w1 = w3 = 1, twiddle-free) fused with the
    // bit-reversed gmem store.
    {
        const int g = tid << 2;
        float2 a = Zc[ZPAD(g)],     b = Zc[ZPAD(g + 1)];
        float2 c = Zc[ZPAD(g + 2)], d = Zc[ZPAD(g + 3)];
        float2 t0v = cadd(a, c);
        float2 t1v = csub(a, c);
        float2 bd  = csub(b, d);
        float2 t3v = make_float2(-bd.y, bd.x);   // i*(b-d)
        float2 t2v = cadd(b, d);

        float2* out2 = reinterpret_cast<float2*>(out + h * LL);
        out2[__brev((unsigned)(g + 0)) >> 22] = cadd(t0v, t2v);
        out2[__brev((unsigned)(g + 1)) >> 22] = csub(t0v, t2v);
        out2[__brev((unsigned)(g + 2)) >> 22] = cadd(t1v, t3v);
        out2[__brev((unsigned)(g + 3)) >> 22] = csub(t1v, t3v);
    }
}

extern "C" void kernel_launch(void* const* d_in, const int* in_sizes, int n_in,
                              void* d_out, int out_size) {
    (void)in_sizes; (void)n_in; (void)out_size;
    const float* C  = (const float*)d_in[0];
    const float* B  = (const float*)d_in[1];
    const float* P  = (const float*)d_in[2];
    const float* W  = (const float*)d_in[3];
    const float* ld = (const float*)d_in[4];
    fused_kernel<<<HH, TPB>>>(C, B, P, W, ld, (float*)d_out);
}